// round 13
// baseline (speedup 1.0000x reference)
#include <cuda_runtime.h>
#include <math.h>

#define BB   32
#define NIN  1024
#define DIN  512
#define NOUT 32
#define DCAP 64
#define FANOUT 2048   // NOUT*DCAP

// packed f32x2 helpers (FFMA2 path — only reachable via PTX)
#define FMA2(acc, a, b) asm("fma.rn.f32x2 %0, %1, %2, %0;" : "+l"(acc) : "l"(a), "l"(b))
#define DUP2(dst, f)    asm("mov.b64 %0, {%1, %1};" : "=l"(dst) : "r"(__float_as_uint(f)))
#define UNPK2(lo, hi, p) asm("mov.b64 {%0, %1}, %2;" : "=r"(lo), "=r"(hi) : "l"(p))

// ---- scratch (device globals; no allocation) ----
__device__ float d_g0p[8*BB*DIN];       // n-split partial sums for g0   (512 KB)
__device__ float d_g [2*BB*NOUT*DIN];   // g partials (2 n-halves)       (4 MB)
__device__ float d_c [BB*NOUT*DIN];     // c[b,o,k] = W_o @ vjn          (2 MB)
__device__ float d_vj[BB*NOUT*DCAP];    // vj[b,o,d]                     (256 KB)
__device__ float d_wv[BB*NOUT*NIN];     // softmax weights Wv[b,o,n]     (4 MB)
__device__ float d_sumsq[2];            // global sum-of-squares of vj per iteration

__device__ __forceinline__ void warp_red_add(float v, float* dst) {
#pragma unroll
    for (int off = 16; off > 0; off >>= 1) v += __shfl_xor_sync(~0u, v, off);
    if ((threadIdx.x & 31) == 0) atomicAdd(dst, v);
}

// ---------------------------------------------------------------------------
// partial[nt][b][k] = sum over 128 n of u[b,n,k]   (grid 32 x 4 x 8)
__global__ void g0_kernel(const float* __restrict__ u) {
    int b = blockIdx.x, kt = blockIdx.y, nt = blockIdx.z;
    if (b == 0 && kt == 0 && nt == 0 && threadIdx.x < 2) d_sumsq[threadIdx.x] = 0.f;
    int k = kt * 128 + threadIdx.x;
    const float* up = u + ((size_t)b * NIN + nt * 128) * DIN + k;
    float acc = 0.f;
#pragma unroll 8
    for (int n = 0; n < 128; n++) acc += up[(size_t)n * DIN];
    d_g0p[(nt * BB + b) * DIN + k] = acc;
}

// vj0[b,j] = sum_k g0[b,k] * W[k,j]; fuses sumsq into slot 0
__global__ void vj0_kernel(const float* __restrict__ W) {
    __shared__ float g0s[4 * DIN];     // 8 KB
    int jt = blockIdx.x, bt = blockIdx.y, tid = threadIdx.x;
    for (int i = 0; i < 8; i++) {
        int e = i * 256 + tid;
        int bl = e >> 9, k = e & 511;
        float s = 0.f;
#pragma unroll
        for (int nt = 0; nt < 8; nt++)
            s += d_g0p[(nt * BB + bt * 4 + bl) * DIN + k];
        g0s[e] = s * (1.0f / 32.0f);
    }
    __syncthreads();
    int j = jt * 256 + tid;
    float acc[4] = {};
#pragma unroll 8
    for (int k = 0; k < DIN; k++) {
        float w = W[(size_t)k * FANOUT + j];
#pragma unroll
        for (int q = 0; q < 4; q++) acc[q] += w * g0s[q * DIN + k];
    }
    float ss = 0.f;
#pragma unroll
    for (int q = 0; q < 4; q++) {
        d_vj[(bt * 4 + q) * FANOUT + j] = acc[q];
        ss += acc[q] * acc[q];
    }
    warp_red_add(ss, &d_sumsq[0]);
}

// ---------------------------------------------------------------------------
// c[b,o,k] = sum_d W[k, o*64+d] * vj[b,o,d] * inv_norm
__global__ void c_kernel(const float* __restrict__ W, int slot) {
    __shared__ float vt[64 * 20];      // [d][bb(16)] pad 20
    __shared__ float ws[128 * 65];     // [kl][d] pad 65
    int o = blockIdx.x, kt = blockIdx.y, bh = blockIdx.z, tid = threadIdx.x;
    float inv = rsqrtf(fmaxf(d_sumsq[slot], 1e-12f));
    for (int i = 0; i < 8; i++) {
        int e = i * 128 + tid;
        int bb = e >> 6, d = e & 63;
        vt[d * 20 + bb] = d_vj[((bh * 16 + bb) * NOUT + o) * DCAP + d] * inv;
    }
    {
        const float* wp = W + (size_t)(kt * 128) * FANOUT + o * DCAP;
        for (int i = 0; i < 16; i++) {
            int e4 = i * 128 + tid;
            int kl = e4 >> 4, dq = e4 & 15;
            float4 v = *(const float4*)&wp[(size_t)kl * FANOUT + dq * 4];
            ws[kl * 65 + dq * 4 + 0] = v.x;
            ws[kl * 65 + dq * 4 + 1] = v.y;
            ws[kl * 65 + dq * 4 + 2] = v.z;
            ws[kl * 65 + dq * 4 + 3] = v.w;
        }
    }
    __syncthreads();
    unsigned long long acc[4][2] = {};
#pragma unroll 4
    for (int d = 0; d < 64; d++) {
        unsigned long long wd; DUP2(wd, ws[tid * 65 + d]);
#pragma unroll
        for (int bq = 0; bq < 4; bq++) {
            ulonglong2 vp = *(const ulonglong2*)&vt[d * 20 + bq * 4];
            FMA2(acc[bq][0], wd, vp.x);
            FMA2(acc[bq][1], wd, vp.y);
        }
    }
    int kg = kt * 128 + tid;
#pragma unroll
    for (int bq = 0; bq < 4; bq++)
#pragma unroll
        for (int p = 0; p < 2; p++) {
            unsigned lo, hi; UNPK2(lo, hi, acc[bq][p]);
            int bb = bh * 16 + bq * 4 + p * 2;
            d_c[(bb * NOUT + o) * DIN + kg]       = __uint_as_float(lo);
            d_c[((bb + 1) * NOUT + o) * DIN + kg] = __uint_as_float(hi);
        }
}

// ---------------------------------------------------------------------------
// fused: b[b,o,n] = sum_k u[b,n,k]*c[b,o,k]; softmax over o; write Wv[b,o,n]
// tile 64n x 32o, 256 threads, 1n x 8o per thread, k-chunk 32,
// register-prefetch double buffering, XOR-swizzled transpose staging.
// grid (32 b x 16 nt) = 512 blocks -> ~3.5 blocks/SM, occ ~43%.
__global__ void route_kernel(const float* __restrict__ u) {
    __shared__ float sa[32 * 68];      // [kk][n^(kq<<2)] stride 68; reused as ts [n][33]
    __shared__ float sc[32 * 36];      // [kk][o]
    int b = blockIdx.x, n0 = blockIdx.y * 64, tid = threadIdx.x;
    int tn = tid & 63, to = tid >> 6;  // n = tn, o = to*8
    unsigned long long acc[4] = {};    // 4 o-pairs
    const float* ub = u + ((size_t)b * NIN + n0) * DIN;
    const float* cb = d_c + b * NOUT * DIN;

    // prefetch chunk 0
    float4 pa[2]; float pc[4];
#pragma unroll
    for (int i = 0; i < 2; i++) {
        int e4 = i * 256 + tid; int n = e4 >> 3, kq = e4 & 7;
        pa[i] = *(const float4*)&ub[(size_t)n * DIN + kq * 4];
    }
#pragma unroll
    for (int i = 0; i < 4; i++) {
        int e = i * 256 + tid; int o = e >> 5, kk = e & 31;
        pc[i] = cb[o * DIN + kk];
    }

    for (int k0 = 0; k0 < DIN; k0 += 32) {
        __syncthreads();
        // swizzled transpose store (conflict-free: banks 20*kq+n+4c all distinct)
#pragma unroll
        for (int i = 0; i < 2; i++) {
            int e4 = i * 256 + tid; int n = e4 >> 3, kq = e4 & 7;
            int colp = n ^ (kq << 2);
            sa[(kq * 4 + 0) * 68 + colp] = pa[i].x;
            sa[(kq * 4 + 1) * 68 + colp] = pa[i].y;
            sa[(kq * 4 + 2) * 68 + colp] = pa[i].z;
            sa[(kq * 4 + 3) * 68 + colp] = pa[i].w;
        }
#pragma unroll
        for (int i = 0; i < 4; i++) {
            int e = i * 256 + tid; int o = e >> 5, kk = e & 31;
            sc[kk * 36 + o] = pc[i];
        }
        __syncthreads();
        int k1 = k0 + 32;
        if (k1 < DIN) {
#pragma unroll
            for (int i = 0; i < 2; i++) {
                int e4 = i * 256 + tid; int n = e4 >> 3, kq = e4 & 7;
                pa[i] = *(const float4*)&ub[(size_t)n * DIN + k1 + kq * 4];
            }
#pragma unroll
            for (int i = 0; i < 4; i++) {
                int e = i * 256 + tid; int o = e >> 5, kk = e & 31;
                pc[i] = cb[o * DIN + k1 + kk];
            }
        }
#pragma unroll
        for (int kk = 0; kk < 32; kk++) {
            float a = sa[kk * 68 + (tn ^ ((kk >> 2) << 2))];               // 1 wf
            ulonglong2 b01 = *(const ulonglong2*)&sc[kk * 36 + to * 8];    // broadcast
            ulonglong2 b23 = *(const ulonglong2*)&sc[kk * 36 + to * 8 + 4];// broadcast
            unsigned long long d0; DUP2(d0, a);
            FMA2(acc[0], d0, b01.x); FMA2(acc[1], d0, b01.y);
            FMA2(acc[2], d0, b23.x); FMA2(acc[3], d0, b23.y);
        }
    }
    __syncthreads();
    // spill logits to ts[n][33] (reusing sa; 64*33=2112 <= 2176)
#pragma unroll
    for (int jp = 0; jp < 4; jp++) {
        unsigned lo, hi; UNPK2(lo, hi, acc[jp]);
        sa[tn * 33 + to * 8 + jp * 2 + 0] = __uint_as_float(lo);
        sa[tn * 33 + to * 8 + jp * 2 + 1] = __uint_as_float(hi);
    }
    __syncthreads();
    {   // softmax over 32 o: quad of threads per n (n = tid>>2, q = tid&3)
        int n = tid >> 2, q = tid & 3;
        float v[8];
        float m = -1e30f;
#pragma unroll
        for (int j = 0; j < 8; j++) {
            v[j] = sa[n * 33 + q * 8 + j];
            m = fmaxf(m, v[j]);
        }
        m = fmaxf(m, __shfl_xor_sync(~0u, m, 1));
        m = fmaxf(m, __shfl_xor_sync(~0u, m, 2));
        float s = 0.f;
#pragma unroll
        for (int j = 0; j < 8; j++) { v[j] = __expf(v[j] - m); s += v[j]; }
        s += __shfl_xor_sync(~0u, s, 1);
        s += __shfl_xor_sync(~0u, s, 2);
        float rs = 1.0f / s;
#pragma unroll
        for (int j = 0; j < 8; j++) sa[n * 33 + q * 8 + j] = v[j] * rs;
    }
    __syncthreads();
#pragma unroll
    for (int i = 0; i < 8; i++) {
        int e = i * 256 + tid; int o = e >> 6, n = e & 63;
        d_wv[(b * NOUT + o) * NIN + n0 + n] = sa[n * 33 + o];
    }
}

// ---------------------------------------------------------------------------
// g partial[z][b,o,k] = sum over 512 n of Wv[b,o,n] * u[b,n,k]
// tile 32o x 64k, 128 threads, 4o x 4k per thread, n-split 2.
// grid (32 b x 8 kt x 2 z) = 512 blocks of 4 warps.
__global__ void g_kernel(const float* __restrict__ u) {
    __shared__ float su[32 * 68];      // [nn][k] pad 68
    __shared__ float sw[32 * 36];      // [nn][o] pad 36
    int b = blockIdx.x, k0 = blockIdx.y * 64, z = blockIdx.z, tid = threadIdx.x;
    int nbase = z * 512, nend = nbase + 512;
    int tk = tid & 15, to = tid >> 4;
    unsigned long long acc[4][2] = {}; // [o][k-pair]
    const float* ub = u + (size_t)b * NIN * DIN + k0;
    const float* wb = d_wv + b * NOUT * NIN;

    // prefetch chunk 0
    float4 pu[4]; float pw[8];
#pragma unroll
    for (int i = 0; i < 4; i++) {
        int e4 = i * 128 + tid; int nn = e4 >> 4, kq = e4 & 15;
        pu[i] = *(const float4*)&ub[(size_t)(nbase + nn) * DIN + kq * 4];
    }
#pragma unroll
    for (int i = 0; i < 8; i++) {
        int e = i * 128 + tid; int o = e >> 5, nn = e & 31;
        pw[i] = wb[o * NIN + nbase + nn];
    }

    for (int n0 = nbase; n0 < nend; n0 += 32) {
        __syncthreads();
#pragma unroll
        for (int i = 0; i < 4; i++) {
            int e4 = i * 128 + tid; int nn = e4 >> 4, kq = e4 & 15;
            *(float4*)&su[nn * 68 + kq * 4] = pu[i];
        }
#pragma unroll
        for (int i = 0; i < 8; i++) {
            int e = i * 128 + tid; int o = e >> 5, nn = e & 31;
            sw[nn * 36 + o] = pw[i];
        }
        __syncthreads();
        int n1 = n0 + 32;
        if (n1 < nend) {
#pragma unroll
            for (int i = 0; i < 4; i++) {
                int e4 = i * 128 + tid; int nn = e4 >> 4, kq = e4 & 15;
                pu[i] = *(const float4*)&ub[(size_t)(n1 + nn) * DIN + kq * 4];
            }
#pragma unroll
            for (int i = 0; i < 8; i++) {
                int e = i * 128 + tid; int o = e >> 5, nn = e & 31;
                pw[i] = wb[o * NIN + n1 + nn];
            }
        }
#pragma unroll
        for (int nn = 0; nn < 32; nn++) {
            ulonglong2 ap = *(const ulonglong2*)&su[nn * 68 + tk * 4];
            float4 wv = *(const float4*)&sw[nn * 36 + to * 4];
            unsigned long long w0, w1, w2, w3;
            DUP2(w0, wv.x); DUP2(w1, wv.y); DUP2(w2, wv.z); DUP2(w3, wv.w);
            FMA2(acc[0][0], w0, ap.x); FMA2(acc[0][1], w0, ap.y);
            FMA2(acc[1][0], w1, ap.x); FMA2(acc[1][1], w1, ap.y);
            FMA2(acc[2][0], w2, ap.x); FMA2(acc[2][1], w2, ap.y);
            FMA2(acc[3][0], w3, ap.x); FMA2(acc[3][1], w3, ap.y);
        }
    }
#pragma unroll
    for (int j = 0; j < 4; j++) {
        unsigned l0, h0, l1, h1;
        UNPK2(l0, h0, acc[j][0]);
        UNPK2(l1, h1, acc[j][1]);
        float4 v = make_float4(__uint_as_float(l0), __uint_as_float(h0),
                               __uint_as_float(l1), __uint_as_float(h1));
        *(float4*)&d_g[((size_t)(z * BB + b) * NOUT + to * 4 + j) * DIN + k0 + tk * 4] = v;
    }
}

// vj[b,o,d] = sum_k (gpart0+gpart1)[b,o,k] * W[k, o*64+d]
__global__ void vj_kernel(const float* __restrict__ W, int slot) {
    __shared__ float gs[8 * DIN];      // 16 KB
    int o = blockIdx.x, bh = blockIdx.y, tid = threadIdx.x;
    for (int i = 0; i < 16; i++) {
        int e = i * 256 + tid;
        int bl = e >> 9, k = e & 511;
        int bb = bh * 8 + bl;
        gs[e] = d_g[((size_t)bb * NOUT + o) * DIN + k]
              + d_g[((size_t)(BB + bb) * NOUT + o) * DIN + k];
    }
    __syncthreads();
    int d2 = tid & 31, bg = tid >> 5;
    const unsigned long long* wp = (const unsigned long long*)(W + o * DCAP + d2 * 2);
    const float* gp = gs + bg * DIN;
    unsigned long long acc = 0ull;
#pragma unroll 8
    for (int k = 0; k < DIN; k++) {
        unsigned long long w = wp[(size_t)k * (FANOUT / 2)];
        unsigned long long gd; DUP2(gd, gp[k]);
        FMA2(acc, w, gd);
    }
    unsigned lo, hi; UNPK2(lo, hi, acc);
    float a0 = __uint_as_float(lo), a1 = __uint_as_float(hi);
    float2* outp = (float2*)&d_vj[((bh * 8 + bg) * NOUT + o) * DCAP + d2 * 2];
    *outp = make_float2(a0, a1);
    if (slot >= 0) warp_red_add(a0 * a0 + a1 * a1, &d_sumsq[slot]);
}

// ---------------------------------------------------------------------------
// squash(vj, axis=-1)
__global__ void squash_kernel(float* __restrict__ out) {
    int bo = blockIdx.x, d = threadIdx.x;
    float v = d_vj[bo * DCAP + d];
    float sq = v * v;
#pragma unroll
    for (int off = 16; off > 0; off >>= 1)
        sq += __shfl_xor_sync(0xffffffffu, sq, off);
    __shared__ float part[2];
    if ((d & 31) == 0) part[d >> 5] = sq;
    __syncthreads();
    float s = part[0] + part[1] + 1e-7f;
    float scale = sqrtf(s) / (0.5f + s);
    out[bo * DCAP + d] = v * scale;
}

// ---------------------------------------------------------------------------
extern "C" void kernel_launch(void* const* d_in, const int* in_sizes, int n_in,
                              void* d_out, int out_size) {
    const float* u = (const float*)d_in[0];   // [32,1024,512]
    const float* W = (const float*)d_in[1];   // [512,2048]
    float* out = (float*)d_out;               // [32,32,64]

    // iter 0: uniform softmax -> column mean of u, project through W
    g0_kernel<<<dim3(32, 4, 8), 128>>>(u);    // also zeroes d_sumsq
    vj0_kernel<<<dim3(8, 8), 256>>>(W);       // sumsq -> slot 0

    // iteration 1
    c_kernel<<<dim3(32, 4, 2), 128>>>(W, 0);
    route_kernel<<<dim3(32, 16), 256>>>(u);
    g_kernel<<<dim3(32, 8, 2), 128>>>(u);
    vj_kernel<<<dim3(32, 4), 256>>>(W, 1);    // sumsq -> slot 1

    // iteration 2
    c_kernel<<<dim3(32, 4, 2), 128>>>(W, 1);
    route_kernel<<<dim3(32, 16), 256>>>(u);
    g_kernel<<<dim3(32, 8, 2), 128>>>(u);
    vj_kernel<<<dim3(32, 4), 256>>>(W, -1);

    squash_kernel<<<1024, 64>>>(out);
}

// round 15
// speedup vs baseline: 1.6096x; 1.6096x over previous
#include <cuda_runtime.h>
#include <math.h>

#define BB   32
#define NIN  1024
#define DIN  512
#define NOUT 32
#define DCAP 64
#define FANOUT 2048   // NOUT*DCAP

// packed f32x2 helpers (FFMA2 path — only reachable via PTX)
#define FMA2(acc, a, b) asm("fma.rn.f32x2 %0, %1, %2, %0;" : "+l"(acc) : "l"(a), "l"(b))
#define DUP2(dst, f)    asm("mov.b64 %0, {%1, %1};" : "=l"(dst) : "r"(__float_as_uint(f)))
#define UNPK2(lo, hi, p) asm("mov.b64 {%0, %1}, %2;" : "=r"(lo), "=r"(hi) : "l"(p))

// ---- scratch (device globals; no allocation) ----
__device__ float d_g0p[8*BB*DIN];       // n-split partial sums for g0   (512 KB)
__device__ float d_g [BB*NOUT*DIN];     // g[b,o,k]                      (2 MB)
__device__ float d_c [BB*NOUT*DIN];     // c[b,o,k] = W_o @ vjn          (2 MB)
__device__ float d_vj[BB*NOUT*DCAP];    // vj[b,o,d]                     (256 KB)
__device__ float d_wv[BB*NOUT*NIN];     // softmax weights Wv[b,o,n]     (4 MB)
__device__ float d_sumsq[2];            // global sum-of-squares of vj per iteration

__device__ __forceinline__ void warp_red_add(float v, float* dst) {
#pragma unroll
    for (int off = 16; off > 0; off >>= 1) v += __shfl_xor_sync(~0u, v, off);
    if ((threadIdx.x & 31) == 0) atomicAdd(dst, v);
}

// ---------------------------------------------------------------------------
// partial[nt][b][k] = sum over 128 n of u[b,n,k]   (grid 32 x 4 x 8)
// block (0,0,0) also zeroes the sumsq slots for this graph replay
__global__ void g0_kernel(const float* __restrict__ u) {
    int b = blockIdx.x, kt = blockIdx.y, nt = blockIdx.z;
    if (b == 0 && kt == 0 && nt == 0 && threadIdx.x < 2) d_sumsq[threadIdx.x] = 0.f;
    int k = kt * 128 + threadIdx.x;
    const float* up = u + ((size_t)b * NIN + nt * 128) * DIN + k;
    float acc = 0.f;
#pragma unroll 8
    for (int n = 0; n < 128; n++) acc += up[(size_t)n * DIN];
    d_g0p[(nt * BB + b) * DIN + k] = acc;
}

// vj0[b,j] = sum_k g0[b,k] * W[k,j]; g0 = (1/32)*sum of 8 partials
// grid (8 jt x 8 bt of 4b), 256 threads; fuses sumsq into slot 0
__global__ void vj0_kernel(const float* __restrict__ W) {
    __shared__ float g0s[4 * DIN];     // 8 KB
    int jt = blockIdx.x, bt = blockIdx.y, tid = threadIdx.x;
    for (int i = 0; i < 8; i++) {
        int e = i * 256 + tid;
        int bl = e >> 9, k = e & 511;
        float s = 0.f;
#pragma unroll
        for (int nt = 0; nt < 8; nt++)
            s += d_g0p[(nt * BB + bt * 4 + bl) * DIN + k];
        g0s[e] = s * (1.0f / 32.0f);
    }
    __syncthreads();
    int j = jt * 256 + tid;
    float acc[4] = {};
#pragma unroll 8
    for (int k = 0; k < DIN; k++) {
        float w = W[(size_t)k * FANOUT + j];
#pragma unroll
        for (int q = 0; q < 4; q++) acc[q] += w * g0s[q * DIN + k];
    }
    float ss = 0.f;
#pragma unroll
    for (int q = 0; q < 4; q++) {
        d_vj[(bt * 4 + q) * FANOUT + j] = acc[q];
        ss += acc[q] * acc[q];
    }
    warp_red_add(ss, &d_sumsq[0]);
}

// ---------------------------------------------------------------------------
// c[b,o,k] = sum_d W[k, o*64+d] * vj[b,o,d] * inv_norm   (norm from d_sumsq[slot])
// grid (32 o x 4 kt x 2 bh of 16b), 128 threads (thread = k), packed over b
__global__ void c_kernel(const float* __restrict__ W, int slot) {
    __shared__ float vt[64 * 20];      // [d][bb(16)] pad 20
    __shared__ float ws[128 * 65];     // [kl][d] pad 65
    int o = blockIdx.x, kt = blockIdx.y, bh = blockIdx.z, tid = threadIdx.x;
    float inv = rsqrtf(fmaxf(d_sumsq[slot], 1e-12f));
    for (int i = 0; i < 8; i++) {
        int e = i * 128 + tid;
        int bb = e >> 6, d = e & 63;
        vt[d * 20 + bb] = d_vj[((bh * 16 + bb) * NOUT + o) * DCAP + d] * inv;
    }
    {
        const float* wp = W + (size_t)(kt * 128) * FANOUT + o * DCAP;
        for (int i = 0; i < 16; i++) {
            int e4 = i * 128 + tid;
            int kl = e4 >> 4, dq = e4 & 15;
            float4 v = *(const float4*)&wp[(size_t)kl * FANOUT + dq * 4];
            ws[kl * 65 + dq * 4 + 0] = v.x;
            ws[kl * 65 + dq * 4 + 1] = v.y;
            ws[kl * 65 + dq * 4 + 2] = v.z;
            ws[kl * 65 + dq * 4 + 3] = v.w;
        }
    }
    __syncthreads();
    unsigned long long acc[4][2] = {};
#pragma unroll 4
    for (int d = 0; d < 64; d++) {
        unsigned long long wd; DUP2(wd, ws[tid * 65 + d]);
#pragma unroll
        for (int bq = 0; bq < 4; bq++) {
            ulonglong2 vp = *(const ulonglong2*)&vt[d * 20 + bq * 4];
            FMA2(acc[bq][0], wd, vp.x);
            FMA2(acc[bq][1], wd, vp.y);
        }
    }
    int kg = kt * 128 + tid;
#pragma unroll
    for (int bq = 0; bq < 4; bq++)
#pragma unroll
        for (int p = 0; p < 2; p++) {
            unsigned lo, hi; UNPK2(lo, hi, acc[bq][p]);
            int bb = bh * 16 + bq * 4 + p * 2;
            d_c[(bb * NOUT + o) * DIN + kg]       = __uint_as_float(lo);
            d_c[((bb + 1) * NOUT + o) * DIN + kg] = __uint_as_float(hi);
        }
}

// ---------------------------------------------------------------------------
// fused: b[b,o,n] = sum_k u[b,n,k]*c[b,o,k]; softmax over o; write Wv[b,o,n]
// tile 128n x 32o, 256 threads, 2n x 8o per thread, k-chunk 32,
// register-prefetch double buffering, XOR-swizzled transpose staging.
// grid (32 b x 8 nt) = 256 blocks.
__global__ void route_kernel(const float* __restrict__ u) {
    __shared__ float sa[32 * 132];     // [kk][n^(kq<<2)] stride 132; reused as ts [n][33]
    __shared__ float sc[32 * 36];      // [kk][o]
    int b = blockIdx.x, n0 = blockIdx.y * 128, tid = threadIdx.x;
    int tn = tid & 63, to = tid >> 6;  // n = tn*2, o = to*8
    unsigned long long acc[2][4] = {}; // [n][o-pair]
    const float* ub = u + ((size_t)b * NIN + n0) * DIN;
    const float* cb = d_c + b * NOUT * DIN;

    // prefetch chunk 0 into registers
    float4 pa[4]; float pc[4];
#pragma unroll
    for (int i = 0; i < 4; i++) {
        int e4 = i * 256 + tid; int n = e4 >> 3, kq = e4 & 7;
        pa[i] = *(const float4*)&ub[(size_t)n * DIN + kq * 4];
    }
#pragma unroll
    for (int i = 0; i < 4; i++) {
        int e = i * 256 + tid; int o = e >> 5, kk = e & 31;
        pc[i] = cb[o * DIN + kk];
    }

    for (int k0 = 0; k0 < DIN; k0 += 32) {
        __syncthreads();   // previous compute done reading smem
        // swizzled transpose store: logical (row=kq*4+c, col=n) at col n^(kq<<2)
#pragma unroll
        for (int i = 0; i < 4; i++) {
            int e4 = i * 256 + tid; int n = e4 >> 3, kq = e4 & 7;
            int colp = n ^ (kq << 2);
            sa[(kq * 4 + 0) * 132 + colp] = pa[i].x;
            sa[(kq * 4 + 1) * 132 + colp] = pa[i].y;
            sa[(kq * 4 + 2) * 132 + colp] = pa[i].z;
            sa[(kq * 4 + 3) * 132 + colp] = pa[i].w;
        }
#pragma unroll
        for (int i = 0; i < 4; i++) {
            int e = i * 256 + tid; int o = e >> 5, kk = e & 31;
            sc[kk * 36 + o] = pc[i];
        }
        __syncthreads();
        int k1 = k0 + 32;
        if (k1 < DIN) {    // issue next chunk's LDGs; latency hidden by compute
#pragma unroll
            for (int i = 0; i < 4; i++) {
                int e4 = i * 256 + tid; int n = e4 >> 3, kq = e4 & 7;
                pa[i] = *(const float4*)&ub[(size_t)n * DIN + k1 + kq * 4];
            }
#pragma unroll
            for (int i = 0; i < 4; i++) {
                int e = i * 256 + tid; int o = e >> 5, kk = e & 31;
                pc[i] = cb[o * DIN + k1 + kk];
            }
        }
#pragma unroll
        for (int kk = 0; kk < 32; kk++) {
            // swizzled a-read: logical cols tn*2, tn*2+1 of row kk
            float2 a2 = *(const float2*)&sa[kk * 132 + ((tn * 2) ^ ((kk >> 2) << 2))];
            ulonglong2 b01 = *(const ulonglong2*)&sc[kk * 36 + to * 8];    // broadcast
            ulonglong2 b23 = *(const ulonglong2*)&sc[kk * 36 + to * 8 + 4];// broadcast
            unsigned long long d0, d1;
            DUP2(d0, a2.x); DUP2(d1, a2.y);
            FMA2(acc[0][0], d0, b01.x); FMA2(acc[0][1], d0, b01.y);
            FMA2(acc[0][2], d0, b23.x); FMA2(acc[0][3], d0, b23.y);
            FMA2(acc[1][0], d1, b01.x); FMA2(acc[1][1], d1, b01.y);
            FMA2(acc[1][2], d1, b23.x); FMA2(acc[1][3], d1, b23.y);
        }
    }
    __syncthreads();
    // spill b-tile to ts[n][o] stride 33 (reusing sa)
#pragma unroll
    for (int i = 0; i < 2; i++)
#pragma unroll
        for (int jp = 0; jp < 4; jp++) {
            unsigned lo, hi; UNPK2(lo, hi, acc[i][jp]);
            sa[(tn * 2 + i) * 33 + to * 8 + jp * 2 + 0] = __uint_as_float(lo);
            sa[(tn * 2 + i) * 33 + to * 8 + jp * 2 + 1] = __uint_as_float(hi);
        }
    __syncthreads();
    if (tid < 128) {   // softmax over 32 o for n = tid
        int n = tid;
        float m = -1e30f;
#pragma unroll
        for (int o = 0; o < 32; o++) m = fmaxf(m, sa[n * 33 + o]);
        float ex[32], s = 0.f;
#pragma unroll
        for (int o = 0; o < 32; o++) { ex[o] = expf(sa[n * 33 + o] - m); s += ex[o]; }
        float rs = 1.0f / s;
#pragma unroll
        for (int o = 0; o < 32; o++) sa[n * 33 + o] = ex[o] * rs;
    }
    __syncthreads();
#pragma unroll
    for (int i = 0; i < 16; i++) {
        int e = i * 256 + tid; int o = e >> 7, n = e & 127;
        d_wv[(b * NOUT + o) * NIN + n0 + n] = sa[n * 33 + o];
    }
}

// ---------------------------------------------------------------------------
// g[b,o,k] = sum_n Wv[b,o,n] * u[b,n,k]
// tile 32o x 64k, 128 threads, 4o x 4k per thread, packed over k,
// register-prefetch double buffering. grid (32 b x 8 kt) = 256 blocks.
__global__ void g_kernel(const float* __restrict__ u) {
    __shared__ float su[32 * 68];      // [nn][k] pad 68
    __shared__ float sw[32 * 36];      // [nn][o] pad 36
    int b = blockIdx.x, k0 = blockIdx.y * 64, tid = threadIdx.x;
    int tk = tid & 15, to = tid >> 4;
    unsigned long long acc[4][2] = {}; // [o][k-pair]
    const float* ub = u + (size_t)b * NIN * DIN + k0;
    const float* wb = d_wv + b * NOUT * NIN;

    // prefetch chunk 0
    float4 pu[4]; float pw[8];
#pragma unroll
    for (int i = 0; i < 4; i++) {
        int e4 = i * 128 + tid; int nn = e4 >> 4, kq = e4 & 15;
        pu[i] = *(const float4*)&ub[(size_t)nn * DIN + kq * 4];
    }
#pragma unroll
    for (int i = 0; i < 8; i++) {
        int e = i * 128 + tid; int o = e >> 5, nn = e & 31;
        pw[i] = wb[o * NIN + nn];
    }

    for (int n0 = 0; n0 < NIN; n0 += 32) {
        __syncthreads();
#pragma unroll
        for (int i = 0; i < 4; i++) {
            int e4 = i * 128 + tid; int nn = e4 >> 4, kq = e4 & 15;
            *(float4*)&su[nn * 68 + kq * 4] = pu[i];
        }
#pragma unroll
        for (int i = 0; i < 8; i++) {
            int e = i * 128 + tid; int o = e >> 5, nn = e & 31;
            sw[nn * 36 + o] = pw[i];
        }
        __syncthreads();
        int n1 = n0 + 32;
        if (n1 < NIN) {
#pragma unroll
            for (int i = 0; i < 4; i++) {
                int e4 = i * 128 + tid; int nn = e4 >> 4, kq = e4 & 15;
                pu[i] = *(const float4*)&ub[(size_t)(n1 + nn) * DIN + kq * 4];
            }
#pragma unroll
            for (int i = 0; i < 8; i++) {
                int e = i * 128 + tid; int o = e >> 5, nn = e & 31;
                pw[i] = wb[o * NIN + n1 + nn];
            }
        }
#pragma unroll
        for (int nn = 0; nn < 32; nn++) {
            ulonglong2 ap = *(const ulonglong2*)&su[nn * 68 + tk * 4];
            float4 wv = *(const float4*)&sw[nn * 36 + to * 4];
            unsigned long long w0, w1, w2, w3;
            DUP2(w0, wv.x); DUP2(w1, wv.y); DUP2(w2, wv.z); DUP2(w3, wv.w);
            FMA2(acc[0][0], w0, ap.x); FMA2(acc[0][1], w0, ap.y);
            FMA2(acc[1][0], w1, ap.x); FMA2(acc[1][1], w1, ap.y);
            FMA2(acc[2][0], w2, ap.x); FMA2(acc[2][1], w2, ap.y);
            FMA2(acc[3][0], w3, ap.x); FMA2(acc[3][1], w3, ap.y);
        }
    }
#pragma unroll
    for (int j = 0; j < 4; j++) {
        unsigned l0, h0, l1, h1;
        UNPK2(l0, h0, acc[j][0]);
        UNPK2(l1, h1, acc[j][1]);
        float4 v = make_float4(__uint_as_float(l0), __uint_as_float(h0),
                               __uint_as_float(l1), __uint_as_float(h1));
        *(float4*)&d_g[(b * NOUT + to * 4 + j) * DIN + k0 + tk * 4] = v;
    }
}

// vj[b,o,d] = sum_k g[b,o,k] * W[k, o*64+d], packed over d
// grid (32 o x 4 bh of 8b), 256 threads = 32 d2 x 8 b.
// slot>=0: write d_vj + fuse sumsq.  out!=null (final iter): fuse squash,
// write result directly (warp = one (b,o) capsule, 64 d across 32 lanes x2).
__global__ void vj_kernel(const float* __restrict__ W, int slot, float* __restrict__ out) {
    __shared__ float gs[8 * DIN];      // 16 KB
    int o = blockIdx.x, bh = blockIdx.y, tid = threadIdx.x;
    for (int i = 0; i < 16; i++) {
        int e = i * 256 + tid;
        int bl = e >> 9, k = e & 511;
        gs[e] = d_g[((bh * 8 + bl) * NOUT + o) * DIN + k];
        (void)bl; (void)k;
    }
    __syncthreads();
    int d2 = tid & 31, bg = tid >> 5;
    const unsigned long long* wp = (const unsigned long long*)(W + o * DCAP + d2 * 2);
    const float* gp = gs + bg * DIN;
    unsigned long long acc = 0ull;
#pragma unroll 8
    for (int k = 0; k < DIN; k++) {
        unsigned long long w = wp[(size_t)k * (FANOUT / 2)];
        unsigned long long gd; DUP2(gd, gp[k]);
        FMA2(acc, w, gd);
    }
    unsigned lo, hi; UNPK2(lo, hi, acc);
    float a0 = __uint_as_float(lo), a1 = __uint_as_float(hi);
    if (out) {
        // fused squash: warp owns capsule (b = bh*8+bg, o); d = d2*2, d2*2+1
        float sq = a0 * a0 + a1 * a1;
#pragma unroll
        for (int off = 16; off > 0; off >>= 1)
            sq += __shfl_xor_sync(0xffffffffu, sq, off);
        float s = sq + 1e-7f;
        float scale = sqrtf(s) / (0.5f + s);
        float2* op = (float2*)&out[((bh * 8 + bg) * NOUT + o) * DCAP + d2 * 2];
        *op = make_float2(a0 * scale, a1 * scale);
    } else {
        float2* outp = (float2*)&d_vj[((bh * 8 + bg) * NOUT + o) * DCAP + d2 * 2];
        *outp = make_float2(a0, a1);
        if (slot >= 0) warp_red_add(a0 * a0 + a1 * a1, &d_sumsq[slot]);
    }
}

// ---------------------------------------------------------------------------
extern "C" void kernel_launch(void* const* d_in, const int* in_sizes, int n_in,
                              void* d_out, int out_size) {
    const float* u = (const float*)d_in[0];   // [32,1024,512]
    const float* W = (const float*)d_in[1];   // [512,2048]
    float* out = (float*)d_out;               // [32,32,64]

    // iter 0: uniform softmax -> column mean of u, project through W
    g0_kernel<<<dim3(32, 4, 8), 128>>>(u);    // also zeroes d_sumsq
    vj0_kernel<<<dim3(8, 8), 256>>>(W);       // fuses sumsq -> slot 0

    // iteration 1
    c_kernel<<<dim3(32, 4, 2), 128>>>(W, 0);
    route_kernel<<<dim3(32, 8), 256>>>(u);
    g_kernel<<<dim3(32, 8), 128>>>(u);
    vj_kernel<<<dim3(32, 4), 256>>>(W, 1, nullptr);  // sumsq -> slot 1

    // iteration 2
    c_kernel<<<dim3(32, 4, 2), 128>>>(W, 1);
    route_kernel<<<dim3(32, 8), 256>>>(u);
    g_kernel<<<dim3(32, 8), 128>>>(u);
    vj_kernel<<<dim3(32, 4), 256>>>(W, -1, out);     // fused squash -> out
}

// round 17
// speedup vs baseline: 1.7297x; 1.0746x over previous
#include <cuda_runtime.h>
#include <math.h>

#define BB   32
#define NIN  1024
#define DIN  512
#define NOUT 32
#define DCAP 64
#define FANOUT 2048   // NOUT*DCAP

// packed f32x2 helpers (FFMA2 path — only reachable via PTX)
#define FMA2(acc, a, b) asm("fma.rn.f32x2 %0, %1, %2, %0;" : "+l"(acc) : "l"(a), "l"(b))
#define DUP2(dst, f)    asm("mov.b64 %0, {%1, %1};" : "=l"(dst) : "r"(__float_as_uint(f)))
#define UNPK2(lo, hi, p) asm("mov.b64 {%0, %1}, %2;" : "=r"(lo), "=r"(hi) : "l"(p))

// ---- scratch (device globals; no allocation) ----
__device__ float d_g0p[8*BB*DIN];       // n-split partial sums for g0   (512 KB)
__device__ float d_g [2*BB*NOUT*DIN];   // g partials (2 n-halves)       (4 MB)
__device__ float d_c [BB*NOUT*DIN];     // c[b,o,k] = W_o @ vjn          (2 MB)
__device__ float d_vj[BB*NOUT*DCAP];    // vj[b,o,d]                     (256 KB)
__device__ float d_wv[BB*NIN*NOUT];     // Wv[b][n][o]  (n-major!)       (4 MB)
__device__ float d_sumsq[2];            // global sum-of-squares of vj per iteration

__device__ __forceinline__ void warp_red_add(float v, float* dst) {
#pragma unroll
    for (int off = 16; off > 0; off >>= 1) v += __shfl_xor_sync(~0u, v, off);
    if ((threadIdx.x & 31) == 0) atomicAdd(dst, v);
}

// ---------------------------------------------------------------------------
// partial[nt][b][k] = sum over 128 n of u[b,n,k]   (grid 32 x 4 x 8)
__global__ void g0_kernel(const float* __restrict__ u) {
    int b = blockIdx.x, kt = blockIdx.y, nt = blockIdx.z;
    if (b == 0 && kt == 0 && nt == 0 && threadIdx.x < 2) d_sumsq[threadIdx.x] = 0.f;
    int k = kt * 128 + threadIdx.x;
    const float* up = u + ((size_t)b * NIN + nt * 128) * DIN + k;
    float acc = 0.f;
#pragma unroll 8
    for (int n = 0; n < 128; n++) acc += up[(size_t)n * DIN];
    d_g0p[(nt * BB + b) * DIN + k] = acc;
}

// vj0[b,j] = sum_k g0[b,k] * W[k,j]; fuses sumsq into slot 0
__global__ void vj0_kernel(const float* __restrict__ W) {
    __shared__ float g0s[4 * DIN];     // 8 KB
    int jt = blockIdx.x, bt = blockIdx.y, tid = threadIdx.x;
    for (int i = 0; i < 8; i++) {
        int e = i * 256 + tid;
        int bl = e >> 9, k = e & 511;
        float s = 0.f;
#pragma unroll
        for (int nt = 0; nt < 8; nt++)
            s += d_g0p[(nt * BB + bt * 4 + bl) * DIN + k];
        g0s[e] = s * (1.0f / 32.0f);
    }
    __syncthreads();
    int j = jt * 256 + tid;
    float acc[4] = {};
#pragma unroll 8
    for (int k = 0; k < DIN; k++) {
        float w = W[(size_t)k * FANOUT + j];
#pragma unroll
        for (int q = 0; q < 4; q++) acc[q] += w * g0s[q * DIN + k];
    }
    float ss = 0.f;
#pragma unroll
    for (int q = 0; q < 4; q++) {
        d_vj[(bt * 4 + q) * FANOUT + j] = acc[q];
        ss += acc[q] * acc[q];
    }
    warp_red_add(ss, &d_sumsq[0]);
}

// ---------------------------------------------------------------------------
// c[b,o,k] = sum_d W[k, o*64+d] * vj[b,o,d] * inv_norm
__global__ void c_kernel(const float* __restrict__ W, int slot) {
    __shared__ float vt[64 * 20];      // [d][bb(16)] pad 20
    __shared__ float ws[128 * 65];     // [kl][d] pad 65
    int o = blockIdx.x, kt = blockIdx.y, bh = blockIdx.z, tid = threadIdx.x;
    float inv = rsqrtf(fmaxf(d_sumsq[slot], 1e-12f));
    for (int i = 0; i < 8; i++) {
        int e = i * 128 + tid;
        int bb = e >> 6, d = e & 63;
        vt[d * 20 + bb] = d_vj[((bh * 16 + bb) * NOUT + o) * DCAP + d] * inv;
    }
    {
        const float* wp = W + (size_t)(kt * 128) * FANOUT + o * DCAP;
        for (int i = 0; i < 16; i++) {
            int e4 = i * 128 + tid;
            int kl = e4 >> 4, dq = e4 & 15;
            float4 v = *(const float4*)&wp[(size_t)kl * FANOUT + dq * 4];
            ws[kl * 65 + dq * 4 + 0] = v.x;
            ws[kl * 65 + dq * 4 + 1] = v.y;
            ws[kl * 65 + dq * 4 + 2] = v.z;
            ws[kl * 65 + dq * 4 + 3] = v.w;
        }
    }
    __syncthreads();
    unsigned long long acc[4][2] = {};
#pragma unroll 4
    for (int d = 0; d < 64; d++) {
        unsigned long long wd; DUP2(wd, ws[tid * 65 + d]);
#pragma unroll
        for (int bq = 0; bq < 4; bq++) {
            ulonglong2 vp = *(const ulonglong2*)&vt[d * 20 + bq * 4];
            FMA2(acc[bq][0], wd, vp.x);
            FMA2(acc[bq][1], wd, vp.y);
        }
    }
    int kg = kt * 128 + tid;
#pragma unroll
    for (int bq = 0; bq < 4; bq++)
#pragma unroll
        for (int p = 0; p < 2; p++) {
            unsigned lo, hi; UNPK2(lo, hi, acc[bq][p]);
            int bb = bh * 16 + bq * 4 + p * 2;
            d_c[(bb * NOUT + o) * DIN + kg]       = __uint_as_float(lo);
            d_c[((bb + 1) * NOUT + o) * DIN + kg] = __uint_as_float(hi);
        }
}

// ---------------------------------------------------------------------------
// fused: b[b,o,n] = sum_k u[b,n,k]*c[b,o,k]; softmax over o; write Wv[b][n][o]
// tile 128n x 32o, 256 threads, 2n x 8o per thread, k-chunk 32,
// register-prefetch double buffering, XOR-swizzled transpose staging.
// grid (32 b x 8 nt) = 256 blocks.
__global__ void route_kernel(const float* __restrict__ u) {
    __shared__ float sa[32 * 132];     // [kk][n^(kq<<2)] stride 132; reused as ts [n][33]
    __shared__ float sc[32 * 36];      // [kk][o]
    int b = blockIdx.x, n0 = blockIdx.y * 128, tid = threadIdx.x;
    int tn = tid & 63, to = tid >> 6;  // n = tn*2, o = to*8
    unsigned long long acc[2][4] = {}; // [n][o-pair]
    const float* ub = u + ((size_t)b * NIN + n0) * DIN;
    const float* cb = d_c + b * NOUT * DIN;

    // prefetch chunk 0 into registers
    float4 pa[4]; float pc[4];
#pragma unroll
    for (int i = 0; i < 4; i++) {
        int e4 = i * 256 + tid; int n = e4 >> 3, kq = e4 & 7;
        pa[i] = *(const float4*)&ub[(size_t)n * DIN + kq * 4];
    }
#pragma unroll
    for (int i = 0; i < 4; i++) {
        int e = i * 256 + tid; int o = e >> 5, kk = e & 31;
        pc[i] = cb[o * DIN + kk];
    }

    for (int k0 = 0; k0 < DIN; k0 += 32) {
        __syncthreads();   // previous compute done reading smem
        // swizzled transpose store: logical (row=kq*4+c, col=n) at col n^(kq<<2)
#pragma unroll
        for (int i = 0; i < 4; i++) {
            int e4 = i * 256 + tid; int n = e4 >> 3, kq = e4 & 7;
            int colp = n ^ (kq << 2);
            sa[(kq * 4 + 0) * 132 + colp] = pa[i].x;
            sa[(kq * 4 + 1) * 132 + colp] = pa[i].y;
            sa[(kq * 4 + 2) * 132 + colp] = pa[i].z;
            sa[(kq * 4 + 3) * 132 + colp] = pa[i].w;
        }
#pragma unroll
        for (int i = 0; i < 4; i++) {
            int e = i * 256 + tid; int o = e >> 5, kk = e & 31;
            sc[kk * 36 + o] = pc[i];
        }
        __syncthreads();
        int k1 = k0 + 32;
        if (k1 < DIN) {    // issue next chunk's LDGs; latency hidden by compute
#pragma unroll
            for (int i = 0; i < 4; i++) {
                int e4 = i * 256 + tid; int n = e4 >> 3, kq = e4 & 7;
                pa[i] = *(const float4*)&ub[(size_t)n * DIN + k1 + kq * 4];
            }
#pragma unroll
            for (int i = 0; i < 4; i++) {
                int e = i * 256 + tid; int o = e >> 5, kk = e & 31;
                pc[i] = cb[o * DIN + k1 + kk];
            }
        }
#pragma unroll
        for (int kk = 0; kk < 32; kk++) {
            // swizzled a-read: logical cols tn*2, tn*2+1 of row kk
            float2 a2 = *(const float2*)&sa[kk * 132 + ((tn * 2) ^ ((kk >> 2) << 2))];
            ulonglong2 b01 = *(const ulonglong2*)&sc[kk * 36 + to * 8];    // broadcast
            ulonglong2 b23 = *(const ulonglong2*)&sc[kk * 36 + to * 8 + 4];// broadcast
            unsigned long long d0, d1;
            DUP2(d0, a2.x); DUP2(d1, a2.y);
            FMA2(acc[0][0], d0, b01.x); FMA2(acc[0][1], d0, b01.y);
            FMA2(acc[0][2], d0, b23.x); FMA2(acc[0][3], d0, b23.y);
            FMA2(acc[1][0], d1, b01.x); FMA2(acc[1][1], d1, b01.y);
            FMA2(acc[1][2], d1, b23.x); FMA2(acc[1][3], d1, b23.y);
        }
    }
    __syncthreads();
    // spill b-tile to ts[n][o] stride 33 (reusing sa)
#pragma unroll
    for (int i = 0; i < 2; i++)
#pragma unroll
        for (int jp = 0; jp < 4; jp++) {
            unsigned lo, hi; UNPK2(lo, hi, acc[i][jp]);
            sa[(tn * 2 + i) * 33 + to * 8 + jp * 2 + 0] = __uint_as_float(lo);
            sa[(tn * 2 + i) * 33 + to * 8 + jp * 2 + 1] = __uint_as_float(hi);
        }
    __syncthreads();
    if (tid < 128) {   // softmax over 32 o for n = tid
        int n = tid;
        float m = -1e30f;
#pragma unroll
        for (int o = 0; o < 32; o++) m = fmaxf(m, sa[n * 33 + o]);
        float ex[32], s = 0.f;
#pragma unroll
        for (int o = 0; o < 32; o++) { ex[o] = expf(sa[n * 33 + o] - m); s += ex[o]; }
        float rs = 1.0f / s;
#pragma unroll
        for (int o = 0; o < 32; o++) sa[n * 33 + o] = ex[o] * rs;
    }
    __syncthreads();
    // write Wv in [b][n][o] layout: lanes span o -> contiguous 128B per warp
#pragma unroll
    for (int i = 0; i < 16; i++) {
        int e = i * 256 + tid; int o = e & 31, n = e >> 5;
        d_wv[((size_t)b * NIN + n0 + n) * NOUT + o] = sa[n * 33 + o];
    }
}

// ---------------------------------------------------------------------------
// g partial[z][b,o,k] = sum over n-half of Wv[b][n][o] * u[b,n,k]
// tile 128k x 32o, 256 threads, 2k x 8o per thread, n-chunk 32.
// su natural [nn][k] layout (k-contiguous reads: no transpose, no swizzle).
// grid (32 b x 4 kt x 2 z) = 256 blocks x 8 warps.
__global__ void g_kernel(const float* __restrict__ u) {
    __shared__ float su[32 * 132];     // [nn][k] pad 132
    __shared__ float sw[32 * 36];      // [nn][o] pad 36
    int b = blockIdx.x, k0 = blockIdx.y * 128, z = blockIdx.z, tid = threadIdx.x;
    int nbase = z * 512;
    int tk = tid & 63, to = tid >> 6;  // k = tk*2, o = to*8
    unsigned long long acc[2][4] = {}; // [k-of-2][o-pair]
    const float* ub = u + (size_t)b * NIN * DIN + k0;
    const float* wb = d_wv + (size_t)b * NIN * NOUT;

    // prefetch chunk 0
    float4 pu[4]; float pw[4];
#pragma unroll
    for (int i = 0; i < 4; i++) {
        int e4 = i * 256 + tid; int nn = e4 >> 5, kq = e4 & 31;
        pu[i] = *(const float4*)&ub[(size_t)(nbase + nn) * DIN + kq * 4];
    }
#pragma unroll
    for (int i = 0; i < 4; i++) {
        int e = i * 256 + tid; int o = e & 31, nn = e >> 5;
        pw[i] = wb[(size_t)(nbase + nn) * NOUT + o];
    }

    for (int n0 = nbase; n0 < nbase + 512; n0 += 32) {
        __syncthreads();
#pragma unroll
        for (int i = 0; i < 4; i++) {
            int e4 = i * 256 + tid; int nn = e4 >> 5, kq = e4 & 31;
            *(float4*)&su[nn * 132 + kq * 4] = pu[i];
        }
#pragma unroll
        for (int i = 0; i < 4; i++) {
            int e = i * 256 + tid; int o = e & 31, nn = e >> 5;
            sw[nn * 36 + o] = pw[i];   // banks (4nn+o)%32, o in lanes: conflict-free
        }
        __syncthreads();
        int n1 = n0 + 32;
        if (n1 < nbase + 512) {
#pragma unroll
            for (int i = 0; i < 4; i++) {
                int e4 = i * 256 + tid; int nn = e4 >> 5, kq = e4 & 31;
                pu[i] = *(const float4*)&ub[(size_t)(n1 + nn) * DIN + kq * 4];
            }
#pragma unroll
            for (int i = 0; i < 4; i++) {
                int e = i * 256 + tid; int o = e & 31, nn = e >> 5;
                pw[i] = wb[(size_t)(n1 + nn) * NOUT + o];
            }
        }
#pragma unroll
        for (int nn = 0; nn < 32; nn++) {
            float2 a2 = *(const float2*)&su[nn * 132 + tk * 2];            // 2 phases
            ulonglong2 b01 = *(const ulonglong2*)&sw[nn * 36 + to * 8];    // broadcast
            ulonglong2 b23 = *(const ulonglong2*)&sw[nn * 36 + to * 8 + 4];// broadcast
            unsigned long long d0, d1;
            DUP2(d0, a2.x); DUP2(d1, a2.y);
            FMA2(acc[0][0], d0, b01.x); FMA2(acc[0][1], d0, b01.y);
            FMA2(acc[0][2], d0, b23.x); FMA2(acc[0][3], d0, b23.y);
            FMA2(acc[1][0], d1, b01.x); FMA2(acc[1][1], d1, b01.y);
            FMA2(acc[1][2], d1, b23.x); FMA2(acc[1][3], d1, b23.y);
        }
    }
    // store: acc[i][p] holds (o=to*8+2p, o+1) for k = k0 + tk*2 + i
    float* gz = d_g + (size_t)(z * BB + b) * NOUT * DIN;
#pragma unroll
    for (int i = 0; i < 2; i++)
#pragma unroll
        for (int p = 0; p < 4; p++) {
            unsigned lo, hi; UNPK2(lo, hi, acc[i][p]);
            int o = to * 8 + p * 2, k = k0 + tk * 2 + i;
            gz[(size_t)o * DIN + k]       = __uint_as_float(lo);
            gz[(size_t)(o + 1) * DIN + k] = __uint_as_float(hi);
        }
}

// ---------------------------------------------------------------------------
// vj[b,o,d] = sum_k (gpart0+gpart1)[b,o,k] * W[k, o*64+d], packed over d
// grid (32 o x 4 bh of 8b), 256 threads = 32 d2 x 8 b.
// slot>=0: write d_vj + fuse sumsq.  out!=null (final iter): fuse squash.
__global__ void vj_kernel(const float* __restrict__ W, int slot, float* __restrict__ out) {
    __shared__ float gs[8 * DIN];      // 16 KB
    int o = blockIdx.x, bh = blockIdx.y, tid = threadIdx.x;
    for (int i = 0; i < 16; i++) {
        int e = i * 256 + tid;
        int bl = e >> 9, k = e & 511;
        int bb = bh * 8 + bl;
        gs[e] = d_g[((size_t)bb * NOUT + o) * DIN + k]
              + d_g[((size_t)(BB + bb) * NOUT + o) * DIN + k];
    }
    __syncthreads();
    int d2 = tid & 31, bg = tid >> 5;
    const unsigned long long* wp = (const unsigned long long*)(W + o * DCAP + d2 * 2);
    const float* gp = gs + bg * DIN;
    unsigned long long acc = 0ull;
#pragma unroll 8
    for (int k = 0; k < DIN; k++) {
        unsigned long long w = wp[(size_t)k * (FANOUT / 2)];
        unsigned long long gd; DUP2(gd, gp[k]);
        FMA2(acc, w, gd);
    }
    unsigned lo, hi; UNPK2(lo, hi, acc);
    float a0 = __uint_as_float(lo), a1 = __uint_as_float(hi);
    if (out) {
        // fused squash: warp owns capsule (b = bh*8+bg, o); d = d2*2, d2*2+1
        float sq = a0 * a0 + a1 * a1;
#pragma unroll
        for (int off = 16; off > 0; off >>= 1)
            sq += __shfl_xor_sync(0xffffffffu, sq, off);
        float s = sq + 1e-7f;
        float scale = sqrtf(s) / (0.5f + s);
        float2* op = (float2*)&out[((bh * 8 + bg) * NOUT + o) * DCAP + d2 * 2];
        *op = make_float2(a0 * scale, a1 * scale);
    } else {
        float2* outp = (float2*)&d_vj[((bh * 8 + bg) * NOUT + o) * DCAP + d2 * 2];
        *outp = make_float2(a0, a1);
        if (slot >= 0) warp_red_add(a0 * a0 + a1 * a1, &d_sumsq[slot]);
    }
}

// ---------------------------------------------------------------------------
extern "C" void kernel_launch(void* const* d_in, const int* in_sizes, int n_in,
                              void* d_out, int out_size) {
    const float* u = (const float*)d_in[0];   // [32,1024,512]
    const float* W = (const float*)d_in[1];   // [512,2048]
    float* out = (float*)d_out;               // [32,32,64]

    // iter 0: uniform softmax -> column mean of u, project through W
    g0_kernel<<<dim3(32, 4, 8), 128>>>(u);    // also zeroes d_sumsq
    vj0_kernel<<<dim3(8, 8), 256>>>(W);       // fuses sumsq -> slot 0

    // iteration 1
    c_kernel<<<dim3(32, 4, 2), 128>>>(W, 0);
    route_kernel<<<dim3(32, 8), 256>>>(u);
    g_kernel<<<dim3(32, 4, 2), 256>>>(u);
    vj_kernel<<<dim3(32, 4), 256>>>(W, 1, nullptr);  // sumsq -> slot 1

    // iteration 2
    c_kernel<<<dim3(32, 4, 2), 128>>>(W, 1);
    route_kernel<<<dim3(32, 8), 256>>>(u);
    g_kernel<<<dim3(32, 4, 2), 256>>>(u);
    vj_kernel<<<dim3(32, 4), 256>>>(W, -1, out);     // fused squash -> out
}